// round 3
// baseline (speedup 1.0000x reference)
#include <cuda_runtime.h>

// out[d] = sum_e alpha_e * (x_src[src_e] @ W^T), alpha = segment_softmax(t/(tau+eps), dst)
// Restructured: y = x_src @ W^T once; out[d] += alpha_e * y[src_e].
// Softmax max-subtraction dropped (scores in [0,2), shift-invariant).
// NOTE: edge_index arrives as int32 (JAX x64 disabled downcasts jnp.int64).

#define TAU_SCALE 1.99999996f  // 1/(0.5+1e-8)
#define MAX_N 100000

__device__ float  g_sum[MAX_N];
__device__ float4 g_y4[(size_t)MAX_N * 16];   // y[n][64] as 16 float4 per row

__global__ void zero_kernel(float* __restrict__ out, int n_out, int n_sum) {
    int i = blockIdx.x * blockDim.x + threadIdx.x;
    if (i < n_out) out[i] = 0.0f;
    if (i < n_sum) g_sum[i] = 0.0f;
}

// y = x @ W^T : each thread owns one row n, W^T staged in smem (broadcast reads).
__global__ __launch_bounds__(256) void gemm_kernel(const float* __restrict__ x,
                                                   const float* __restrict__ W,
                                                   int N) {
    __shared__ float WTs[64 * 64];  // WTs[k*64+h] = W[h*64+k]
    int t = threadIdx.x;
    for (int i = t; i < 4096; i += 256) {
        int h = i >> 6, k = i & 63;
        WTs[k * 64 + h] = W[i];
    }
    __syncthreads();

    int n = blockIdx.x * 256 + t;
    if (n >= N) return;

    float acc[64];
#pragma unroll
    for (int h = 0; h < 64; h++) acc[h] = 0.0f;

    const float4* xp = (const float4*)(x + (size_t)n * 64);
#pragma unroll 4
    for (int k4 = 0; k4 < 16; k4++) {
        float4 a = xp[k4];
        float av[4] = {a.x, a.y, a.z, a.w};
#pragma unroll
        for (int kk = 0; kk < 4; kk++) {
            const float4* wr = (const float4*)(WTs + (k4 * 4 + kk) * 64);
#pragma unroll
            for (int h4 = 0; h4 < 16; h4++) {
                float4 w = wr[h4];
                acc[h4 * 4 + 0] += av[kk] * w.x;
                acc[h4 * 4 + 1] += av[kk] * w.y;
                acc[h4 * 4 + 2] += av[kk] * w.z;
                acc[h4 * 4 + 3] += av[kk] * w.w;
            }
        }
    }

    float4* yp = g_y4 + (size_t)n * 16;
#pragma unroll
    for (int h4 = 0; h4 < 16; h4++)
        yp[h4] = make_float4(acc[h4 * 4 + 0], acc[h4 * 4 + 1],
                             acc[h4 * 4 + 2], acc[h4 * 4 + 3]);
}

// Per-edge: g_sum[dst] += exp(score)
__global__ void sum_kernel(const int* __restrict__ ei,
                           const float* __restrict__ tt, int E) {
    int e = blockIdx.x * blockDim.x + threadIdx.x;
    if (e >= E) return;
    int d = ei[E + e];
    atomicAdd(&g_sum[d], __expf(tt[e] * TAU_SCALE));
}

// 16 threads per edge. Group leader (j==0) loads src/dst/t, computes alpha;
// shuffles broadcast to the group. Each thread handles one float4 of the row
// with 4 scalar atomicAdds (REDG.ADD.F32 — fire-and-forget).
__global__ void scatter_kernel(const int* __restrict__ ei,
                               const float* __restrict__ tt,
                               float* __restrict__ out, int E) {
    int tid = blockIdx.x * blockDim.x + threadIdx.x;
    int e = tid >> 4;
    int j = tid & 15;
    int lane = threadIdx.x & 31;
    bool valid = (e < E);

    int s = 0, d = 0;
    float a = 0.0f;
    if (valid && j == 0) {
        s = ei[e];
        d = ei[E + e];
        a = __expf(tt[e] * TAU_SCALE) / (g_sum[d] + 1e-16f);
    }
    // group leaders are lanes 0 and 16
    s = __shfl_sync(0xffffffffu, s, lane & 16);
    d = __shfl_sync(0xffffffffu, d, lane & 16);
    a = __shfl_sync(0xffffffffu, a, lane & 16);
    if (!valid) return;

    float4 v = g_y4[(size_t)s * 16 + j];
    float* p = out + (size_t)d * 64 + (size_t)j * 4;
    atomicAdd(p + 0, a * v.x);
    atomicAdd(p + 1, a * v.y);
    atomicAdd(p + 2, a * v.z);
    atomicAdd(p + 3, a * v.w);
}

extern "C" void kernel_launch(void* const* d_in, const int* in_sizes, int n_in,
                              void* d_out, int out_size) {
    const float* x_src = (const float*)d_in[0];
    // d_in[1] = x_dst (only defines N_dst via its size)
    const float* W     = (const float*)d_in[2];
    const int*   ei    = (const int*)d_in[3];   // int32! (JAX x64 off)
    const float* tt    = (const float*)d_in[4];
    float*       out   = (float*)d_out;

    int n_src = in_sizes[0] / 64;
    int n_dst = in_sizes[1] / 64;
    int E     = in_sizes[4];

    int n_out = n_dst * 64;
    zero_kernel<<<(n_out + 255) / 256, 256>>>(out, n_out, n_dst);
    gemm_kernel<<<(n_src + 255) / 256, 256>>>(x_src, W, n_src);
    sum_kernel<<<(E + 255) / 256, 256>>>(ei, tt, E);

    long long total = (long long)E * 16;
    int blocks = (int)((total + 255) / 256);
    scatter_kernel<<<blocks, 256>>>(ei, tt, out, E);
}

// round 5
// speedup vs baseline: 1.4490x; 1.4490x over previous
#include <cuda_runtime.h>

// out[d] = sum_e alpha_e * (x_src[src_e] @ W^T), alpha = segment_softmax(t/(tau+eps), dst)
// Restructured: y = x_src @ W^T once; out[d] += alpha_e * y[src_e].
// Softmax max-subtraction dropped (scores in [0,2), shift-invariant).
// edge_index arrives as int32 (JAX x64 disabled downcasts jnp.int64).

#define TAU_SCALE 1.99999996f  // 1/(0.5+1e-8)
#define MAX_N 100000

__device__ float  g_sum[MAX_N];
__device__ float4 g_y4[(size_t)MAX_N * 16];   // y[n][64] as 16 float4 per row

__global__ void zero_kernel(float* __restrict__ out, int n_out, int n_sum) {
    int i = blockIdx.x * blockDim.x + threadIdx.x;
    if (i < n_out) out[i] = 0.0f;
    if (i < n_sum) g_sum[i] = 0.0f;
}

// y = x @ W^T : each thread owns one row n, W^T staged in smem (broadcast reads).
__global__ __launch_bounds__(256) void gemm_kernel(const float* __restrict__ x,
                                                   const float* __restrict__ W,
                                                   int N) {
    __shared__ float WTs[64 * 64];  // WTs[k*64+h] = W[h*64+k]
    int t = threadIdx.x;
    for (int i = t; i < 4096; i += 256) {
        int h = i >> 6, k = i & 63;
        WTs[k * 64 + h] = W[i];
    }
    __syncthreads();

    int n = blockIdx.x * 256 + t;
    if (n >= N) return;

    float acc[64];
#pragma unroll
    for (int h = 0; h < 64; h++) acc[h] = 0.0f;

    const float4* xp = (const float4*)(x + (size_t)n * 64);
#pragma unroll 4
    for (int k4 = 0; k4 < 16; k4++) {
        float4 a = xp[k4];
        float av[4] = {a.x, a.y, a.z, a.w};
#pragma unroll
        for (int kk = 0; kk < 4; kk++) {
            const float4* wr = (const float4*)(WTs + (k4 * 4 + kk) * 64);
#pragma unroll
            for (int h4 = 0; h4 < 16; h4++) {
                float4 w = wr[h4];
                acc[h4 * 4 + 0] += av[kk] * w.x;
                acc[h4 * 4 + 1] += av[kk] * w.y;
                acc[h4 * 4 + 2] += av[kk] * w.z;
                acc[h4 * 4 + 3] += av[kk] * w.w;
            }
        }
    }

    float4* yp = g_y4 + (size_t)n * 16;
#pragma unroll
    for (int h4 = 0; h4 < 16; h4++)
        yp[h4] = make_float4(acc[h4 * 4 + 0], acc[h4 * 4 + 1],
                             acc[h4 * 4 + 2], acc[h4 * 4 + 3]);
}

// Per-edge: g_sum[dst] += exp(score)
__global__ void sum_kernel(const int* __restrict__ ei,
                           const float* __restrict__ tt, int E) {
    int e = blockIdx.x * blockDim.x + threadIdx.x;
    if (e >= E) return;
    int d = ei[E + e];
    atomicAdd(&g_sum[d], __expf(tt[e] * TAU_SCALE));
}

// 16 threads per edge. Group leader (j==0) loads src/dst/t, computes alpha;
// shuffles broadcast (s, d, alpha) to the group. Each thread handles one
// float4 of the 64-wide row with a single red.global.add.v4.f32.
__global__ void scatter_kernel(const int* __restrict__ ei,
                               const float* __restrict__ tt,
                               float* __restrict__ out, int E) {
    int tid = blockIdx.x * blockDim.x + threadIdx.x;
    int e = tid >> 4;
    int j = tid & 15;
    int lane = threadIdx.x & 31;
    bool valid = (e < E);

    int s = 0, d = 0;
    float a = 0.0f;
    if (valid && j == 0) {
        s = ei[e];
        d = ei[E + e];
        a = __expf(tt[e] * TAU_SCALE) / (g_sum[d] + 1e-16f);
    }
    // group leaders are lanes 0 and 16
    s = __shfl_sync(0xffffffffu, s, lane & 16);
    d = __shfl_sync(0xffffffffu, d, lane & 16);
    a = __shfl_sync(0xffffffffu, a, lane & 16);
    if (!valid) return;

    float4 v = g_y4[(size_t)s * 16 + j];
    float* p = out + (size_t)d * 64 + (size_t)j * 4;
    asm volatile("red.global.add.v4.f32 [%0], {%1,%2,%3,%4};"
                 :: "l"(p), "f"(a * v.x), "f"(a * v.y), "f"(a * v.z), "f"(a * v.w)
                 : "memory");
}

extern "C" void kernel_launch(void* const* d_in, const int* in_sizes, int n_in,
                              void* d_out, int out_size) {
    const float* x_src = (const float*)d_in[0];
    // d_in[1] = x_dst (only defines N_dst via its size)
    const float* W     = (const float*)d_in[2];
    const int*   ei    = (const int*)d_in[3];   // int32! (JAX x64 off)
    const float* tt    = (const float*)d_in[4];
    float*       out   = (float*)d_out;

    int n_src = in_sizes[0] / 64;
    int n_dst = in_sizes[1] / 64;
    int E     = in_sizes[4];

    int n_out = n_dst * 64;
    zero_kernel<<<(n_out + 255) / 256, 256>>>(out, n_out, n_dst);
    sum_kernel<<<(E + 255) / 256, 256>>>(ei, tt, E);
    gemm_kernel<<<(n_src + 255) / 256, 256>>>(x_src, W, n_src);

    long long total = (long long)E * 16;
    int blocks = (int)((total + 255) / 256);
    scatter_kernel<<<blocks, 256>>>(ei, tt, out, E);
}